// round 1
// baseline (speedup 1.0000x reference)
#include <cuda_runtime.h>
#include <math.h>

#define HW   16384
#define Bn   8
#define Cn   64
#define HIDn 170

// ---------------- scratch (static device memory; no allocations) ----------------
__device__ float g_bufA[Bn * Cn * HW];      // generic 64-ch buffer (LN out / attn out)
__device__ float g_bufR[Bn * Cn * HW];      // RSA proj out (x_)
__device__ float g_bufX[Bn * Cn * HW];      // x after spatial FFN
__device__ float g_bufG[Bn * Cn * HW];      // GSA proj out (x_)
__device__ float g_big1[Bn * 340 * HW];     // up to 340 channels
__device__ float g_big2[Bn * 340 * HW];
__device__ float g_attn[Bn * 8 * 8 * 8];    // GSA attention matrices

__device__ __forceinline__ float gelu_f(float x) {
    return 0.5f * x * (1.0f + erff(x * 0.70710678118654752f));
}

// ---------------- LayerNorm over channels (optional fused add of 2nd tensor) ----
__global__ void ln_kernel(const float* __restrict__ in, const float* __restrict__ addp,
                          const float* __restrict__ w, const float* __restrict__ bvec,
                          float* __restrict__ out)
{
    int gid = blockIdx.x * blockDim.x + threadIdx.x;   // over B*HW
    int b = gid >> 14;
    int p = gid & (HW - 1);
    int base = b * Cn * HW + p;
    float v[Cn];
    float s = 0.f;
    if (addp) {
        #pragma unroll
        for (int c = 0; c < Cn; c++) {
            float t = in[base + c * HW] + addp[base + c * HW];
            v[c] = t; s += t;
        }
    } else {
        #pragma unroll
        for (int c = 0; c < Cn; c++) {
            float t = in[base + c * HW];
            v[c] = t; s += t;
        }
    }
    float mu = s * (1.0f / Cn);
    float var = 0.f;
    #pragma unroll
    for (int c = 0; c < Cn; c++) { float d = v[c] - mu; var += d * d; }
    var *= (1.0f / Cn);
    float rs = rsqrtf(var + 1e-5f);
    #pragma unroll
    for (int c = 0; c < Cn; c++)
        out[base + c * HW] = (v[c] - mu) * rs * w[c] + bvec[c];
}

// ---------------- 1x1 conv as tiled GEMM ----------------------------------------
// out[b,o,p] = sum_c wt[o,c] * X[b,c,remap(p)]  (+ resid[b,o,p])
// shift: circular roll folded into input pixel index.
// gated: X[c] = gelu(in[c]) * in[c+HID]   (Cin = HID, physical channels inCh = 2*HID)
#define TP 64
#define TO 64
#define KC 16
__global__ void conv1x1_kernel(const float* __restrict__ in, const float* __restrict__ wt,
                               float* __restrict__ out, const float* __restrict__ resid,
                               int Cin, int Cout, int inCh, int shift, int gated)
{
    __shared__ float Xs[KC][TP];
    __shared__ float Ws[KC][TO];
    int b  = blockIdx.z;
    int p0 = blockIdx.x * TP;
    int o0 = blockIdx.y * TO;
    int tid = threadIdx.x;           // 256 threads
    int tx = tid & 15;               // pixel micro-tile (4 px)
    int ty = tid >> 4;               // out-channel micro-tile (4 ch)
    float acc[4][4] = {};
    const float* inb = in + (size_t)b * inCh * HW;

    for (int k0 = 0; k0 < Cin; k0 += KC) {
        // stage X tile
        for (int e = tid; e < KC * TP; e += 256) {
            int kk = e >> 6, tp = e & 63;
            int c = k0 + kk;
            float v = 0.f;
            if (c < Cin) {
                int p = p0 + tp;
                int ip = p;
                if (shift) {
                    int h = (p >> 7) + shift, w = (p & 127) + shift;
                    ip = ((h & 127) << 7) | (w & 127);
                }
                if (gated) {
                    float a = inb[c * HW + ip];
                    float g = inb[(c + HIDn) * HW + ip];
                    v = gelu_f(a) * g;
                } else {
                    v = inb[c * HW + ip];
                }
            }
            Xs[kk][tp] = v;
        }
        // stage W tile
        for (int e = tid; e < KC * TO; e += 256) {
            int kk = e >> 6, oo = e & 63;
            int o = o0 + oo, c = k0 + kk;
            Ws[kk][oo] = (o < Cout && c < Cin) ? wt[o * Cin + c] : 0.f;
        }
        __syncthreads();
        #pragma unroll
        for (int kk = 0; kk < KC; kk++) {
            float4 xv = *(const float4*)(&Xs[kk][tx << 2]);
            float4 wv = *(const float4*)(&Ws[kk][ty << 2]);
            acc[0][0] += wv.x * xv.x; acc[0][1] += wv.x * xv.y; acc[0][2] += wv.x * xv.z; acc[0][3] += wv.x * xv.w;
            acc[1][0] += wv.y * xv.x; acc[1][1] += wv.y * xv.y; acc[1][2] += wv.y * xv.z; acc[1][3] += wv.y * xv.w;
            acc[2][0] += wv.z * xv.x; acc[2][1] += wv.z * xv.y; acc[2][2] += wv.z * xv.z; acc[2][3] += wv.z * xv.w;
            acc[3][0] += wv.w * xv.x; acc[3][1] += wv.w * xv.y; acc[3][2] += wv.w * xv.z; acc[3][3] += wv.w * xv.w;
        }
        __syncthreads();
    }
    #pragma unroll
    for (int i = 0; i < 4; i++) {
        int o = o0 + (ty << 2) + i;
        if (o < Cout) {
            int ob = b * Cout * HW + o * HW + p0 + (tx << 2);
            #pragma unroll
            for (int j = 0; j < 4; j++) {
                float v = acc[i][j];
                if (resid) v += resid[ob + j];
                out[ob + j] = v;
            }
        }
    }
}

// ---------------- depthwise 3x3 conv, zero padding -------------------------------
__global__ void dwconv_kernel(const float* __restrict__ in, const float* __restrict__ wt,
                              float* __restrict__ out, int Ch)
{
    int c = blockIdx.y, b = blockIdx.z;
    int p = blockIdx.x * 256 + threadIdx.x;
    int h = p >> 7, w = p & 127;
    const float* ib = in + ((size_t)b * Ch + c) * HW;
    const float* wc = wt + c * 9;
    float s = 0.f;
    #pragma unroll
    for (int dy = -1; dy <= 1; dy++) {
        int hh = h + dy;
        if (hh < 0 || hh > 127) continue;
        #pragma unroll
        for (int dx = -1; dx <= 1; dx++) {
            int ww = w + dx;
            if (ww < 0 || ww > 127) continue;
            s += wc[(dy + 1) * 3 + (dx + 1)] * ib[(hh << 7) | ww];
        }
    }
    out[((size_t)b * Ch + c) * HW + p] = s;
}

// ---------------- RSA window attention (one 8x8 window per block) ----------------
// qkv layout: [b][192][HW] in the ROLLED frame. out: [b][64][HW] rolled frame.
__global__ void rsa_attn_kernel(const float* __restrict__ qkv, float* __restrict__ out,
                                const float* __restrict__ temp)
{
    extern __shared__ float sm[];
    float* qT  = sm;               // [64][64]  (q, later v)
    float* kT  = sm + 4096;        // [64][65]
    float* ats = kT + 64 * 65;     // [64][65]
    float* inv = ats + 64 * 65;    // [64]
    int blk = blockIdx.x;
    int b   = blk >> 8;
    int win = blk & 255;
    int wy = win >> 4, wx = win & 15;
    int tid = threadIdx.x;
    int qbase = b * 192 * HW;

    for (int e = tid; e < 4096; e += 256) {
        int c = e >> 6, p = e & 63;
        int gp = (((wy << 3) + (p >> 3)) << 7) | ((wx << 3) + (p & 7));
        qT[c * 64 + p] = qkv[qbase + c * HW + gp];
        kT[c * 65 + p] = qkv[qbase + (64 + c) * HW + gp];
    }
    __syncthreads();
    if (tid < 64) {
        int p = tid;
        float nq = 0.f, nk = 0.f;
        #pragma unroll
        for (int c = 0; c < 64; c++) {
            float a = qT[c * 64 + p]; nq += a * a;
            float bb = kT[c * 65 + p]; nk += bb * bb;
        }
        float dq = fmaxf(sqrtf(nq), 1e-12f);
        float dk = fmaxf(sqrtf(nk), 1e-12f);
        inv[p] = 1.0f / (dq * dk);
    }
    __syncthreads();
    for (int e = tid; e < 4096; e += 256) {
        int d = e >> 6, p = e & 63;
        kT[d * 65 + p] *= inv[p];
    }
    __syncthreads();
    float tscale = temp[0];
    {
        int c0 = (tid >> 4) << 2, d0 = (tid & 15) << 2;
        float s[4][4] = {};
        for (int p = 0; p < 64; p++) {
            float qv[4], kv[4];
            #pragma unroll
            for (int i = 0; i < 4; i++) qv[i] = qT[(c0 + i) * 64 + p];
            #pragma unroll
            for (int j = 0; j < 4; j++) kv[j] = kT[(d0 + j) * 65 + p];
            #pragma unroll
            for (int i = 0; i < 4; i++)
                #pragma unroll
                for (int j = 0; j < 4; j++) s[i][j] += qv[i] * kv[j];
        }
        #pragma unroll
        for (int i = 0; i < 4; i++)
            #pragma unroll
            for (int j = 0; j < 4; j++)
                ats[(c0 + i) * 65 + (d0 + j)] = fmaxf(0.f, tscale * s[i][j]);
    }
    __syncthreads();
    // overwrite qT with v
    for (int e = tid; e < 4096; e += 256) {
        int c = e >> 6, p = e & 63;
        int gp = (((wy << 3) + (p >> 3)) << 7) | ((wx << 3) + (p & 7));
        qT[c * 64 + p] = qkv[qbase + (128 + c) * HW + gp];
    }
    __syncthreads();
    {
        int p0 = (tid >> 4) << 2, d0 = (tid & 15) << 2;
        float s[4][4] = {};
        for (int c = 0; c < 64; c++) {
            float vv[4], av[4];
            #pragma unroll
            for (int i = 0; i < 4; i++) vv[i] = qT[c * 64 + p0 + i];
            #pragma unroll
            for (int j = 0; j < 4; j++) av[j] = ats[c * 65 + d0 + j];
            #pragma unroll
            for (int i = 0; i < 4; i++)
                #pragma unroll
                for (int j = 0; j < 4; j++) s[i][j] += vv[i] * av[j];
        }
        int obase = b * 64 * HW;
        #pragma unroll
        for (int i = 0; i < 4; i++) {
            int p = p0 + i;
            int gp = (((wy << 3) + (p >> 3)) << 7) | ((wx << 3) + (p & 7));
            #pragma unroll
            for (int j = 0; j < 4; j++)
                out[obase + (d0 + j) * HW + gp] = s[i][j];
        }
    }
}

// ---------------- GSA: attention matrices (one block per (b,head)) ---------------
__global__ void gsa_attn_kernel(const float* __restrict__ qkv, float* __restrict__ attn,
                                const float* __restrict__ temp)
{
    __shared__ float red[8][80];
    __shared__ float fin[80];
    int b = blockIdx.x >> 3, hd = blockIdx.x & 7;
    int tid = threadIdx.x;
    const float* qb = qkv + ((size_t)b * 192 + hd * 8) * HW;
    const float* kb = qkv + ((size_t)b * 192 + 64 + hd * 8) * HW;
    float dot[8][8] = {};
    float qn[8] = {}, kn[8] = {};
    for (int n = tid; n < HW; n += 256) {
        float qv[8], kv[8];
        #pragma unroll
        for (int i = 0; i < 8; i++) { qv[i] = qb[i * HW + n]; kv[i] = kb[i * HW + n]; }
        #pragma unroll
        for (int i = 0; i < 8; i++) { qn[i] += qv[i] * qv[i]; kn[i] += kv[i] * kv[i]; }
        #pragma unroll
        for (int i = 0; i < 8; i++)
            #pragma unroll
            for (int j = 0; j < 8; j++) dot[i][j] += qv[i] * kv[j];
    }
    int lane = tid & 31, wid = tid >> 5;
    #pragma unroll
    for (int i = 0; i < 8; i++)
        #pragma unroll
        for (int j = 0; j < 8; j++) {
            float v = dot[i][j];
            #pragma unroll
            for (int off = 16; off; off >>= 1) v += __shfl_xor_sync(0xffffffffu, v, off);
            if (lane == 0) red[wid][i * 8 + j] = v;
        }
    #pragma unroll
    for (int i = 0; i < 8; i++) {
        float v = qn[i];
        #pragma unroll
        for (int off = 16; off; off >>= 1) v += __shfl_xor_sync(0xffffffffu, v, off);
        if (lane == 0) red[wid][64 + i] = v;
        float u = kn[i];
        #pragma unroll
        for (int off = 16; off; off >>= 1) u += __shfl_xor_sync(0xffffffffu, u, off);
        if (lane == 0) red[wid][72 + i] = u;
    }
    __syncthreads();
    if (tid < 80) {
        float s = 0.f;
        #pragma unroll
        for (int w2 = 0; w2 < 8; w2++) s += red[w2][tid];
        fin[tid] = s;
    }
    __syncthreads();
    if (tid < 64) {
        int c = tid >> 3, d = tid & 7;
        float nq = fmaxf(sqrtf(fin[64 + c]), 1e-12f);
        float nk = fmaxf(sqrtf(fin[72 + d]), 1e-12f);
        float a = fmaxf(0.f, temp[0] * fin[tid] / (nq * nk));
        attn[((b * 8 + hd) * 8 + c) * 8 + d] = a;
    }
}

// ---------------- GSA: apply attention to v, with (head,c)->(c*8+head) reorder ---
__global__ void gsa_apply_kernel(const float* __restrict__ qkv, const float* __restrict__ attn,
                                 float* __restrict__ out)
{
    __shared__ float at[512];
    int b = blockIdx.y;
    int tid = threadIdx.x;
    for (int e = tid; e < 512; e += 256) at[e] = attn[b * 512 + e];
    __syncthreads();
    int n = blockIdx.x * 256 + tid;
    const float* vb = qkv + ((size_t)b * 192 + 128) * HW + n;
    float* ob = out + (size_t)b * 64 * HW + n;
    #pragma unroll
    for (int hd = 0; hd < 8; hd++) {
        float vv[8];
        #pragma unroll
        for (int d = 0; d < 8; d++) vv[d] = vb[(hd * 8 + d) * HW];
        #pragma unroll
        for (int cc = 0; cc < 8; cc++) {
            float s = 0.f;
            #pragma unroll
            for (int d = 0; d < 8; d++) s += at[hd * 64 + cc * 8 + d] * vv[d];
            ob[(cc * 8 + hd) * HW] = s;
        }
    }
}

// ---------------- launch ---------------------------------------------------------
extern "C" void kernel_launch(void* const* d_in, const int* in_sizes, int n_in,
                              void* d_out, int out_size)
{
    const float* x         = (const float*)d_in[0];
    const float* ln_s0_w   = (const float*)d_in[1];
    const float* ln_s0_b   = (const float*)d_in[2];
    const float* ln_s2_w   = (const float*)d_in[3];
    const float* ln_s2_b   = (const float*)d_in[4];
    const float* rsa_qkv_w = (const float*)d_in[5];
    const float* rsa_dw_w  = (const float*)d_in[6];
    const float* rsa_proj_w= (const float*)d_in[7];
    const float* rsa_temp  = (const float*)d_in[8];
    const float* ffs_in_w  = (const float*)d_in[9];
    const float* ffs_dw_w  = (const float*)d_in[10];
    const float* ffs_out_w = (const float*)d_in[11];
    const float* ln_c0_w   = (const float*)d_in[12];
    const float* ln_c0_b   = (const float*)d_in[13];
    const float* ln_c2_w   = (const float*)d_in[14];
    const float* ln_c2_b   = (const float*)d_in[15];
    const float* gsa_qkv_w = (const float*)d_in[16];
    const float* gsa_dw_w  = (const float*)d_in[17];
    const float* gsa_proj_w= (const float*)d_in[18];
    const float* gsa_temp  = (const float*)d_in[19];
    const float* ffc_in_w  = (const float*)d_in[20];
    const float* ffc_dw_w  = (const float*)d_in[21];
    const float* ffc_out_w = (const float*)d_in[22];
    float* outp = (float*)d_out;

    float *bufA, *bufR, *bufX, *bufG, *big1, *big2, *attnb;
    cudaGetSymbolAddress((void**)&bufA,  g_bufA);
    cudaGetSymbolAddress((void**)&bufR,  g_bufR);
    cudaGetSymbolAddress((void**)&bufX,  g_bufX);
    cudaGetSymbolAddress((void**)&bufG,  g_bufG);
    cudaGetSymbolAddress((void**)&big1,  g_big1);
    cudaGetSymbolAddress((void**)&big2,  g_big2);
    cudaGetSymbolAddress((void**)&attnb, g_attn);

    const int rsa_smem = (4096 + 64 * 65 * 2 + 64) * (int)sizeof(float);  // 49920 B
    cudaFuncSetAttribute(rsa_attn_kernel, cudaFuncAttributeMaxDynamicSharedMemorySize, rsa_smem);

    // ---- stage 1: RSA + spatial FFN ----
    ln_kernel<<<512, 256>>>(x, nullptr, ln_s0_w, ln_s0_b, bufA);
    conv1x1_kernel<<<dim3(256, 3, Bn), 256>>>(bufA, rsa_qkv_w, big1, nullptr, 64, 192, 64,  4, 0);
    dwconv_kernel<<<dim3(64, 192, Bn), 256>>>(big1, rsa_dw_w, big2, 192);
    rsa_attn_kernel<<<Bn * 256, 256, rsa_smem>>>(big2, bufA, rsa_temp);
    conv1x1_kernel<<<dim3(256, 1, Bn), 256>>>(bufA, rsa_proj_w, bufR, nullptr, 64, 64, 64, -4, 0);
    ln_kernel<<<512, 256>>>(bufR, x, ln_s2_w, ln_s2_b, bufA);
    conv1x1_kernel<<<dim3(256, 6, Bn), 256>>>(bufA, ffs_in_w, big1, nullptr, 64, 340, 64, 0, 0);
    dwconv_kernel<<<dim3(64, 340, Bn), 256>>>(big1, ffs_dw_w, big2, 340);
    conv1x1_kernel<<<dim3(256, 1, Bn), 256>>>(big2, ffs_out_w, bufX, bufR, HIDn, 64, 340, 0, 1);

    // ---- stage 2: GSA + channel FFN ----
    ln_kernel<<<512, 256>>>(bufX, nullptr, ln_c0_w, ln_c0_b, bufA);
    conv1x1_kernel<<<dim3(256, 3, Bn), 256>>>(bufA, gsa_qkv_w, big1, nullptr, 64, 192, 64, 0, 0);
    dwconv_kernel<<<dim3(64, 192, Bn), 256>>>(big1, gsa_dw_w, big2, 192);
    gsa_attn_kernel<<<64, 256>>>(big2, attnb, gsa_temp);
    gsa_apply_kernel<<<dim3(64, Bn), 256>>>(big2, attnb, bufA);
    conv1x1_kernel<<<dim3(256, 1, Bn), 256>>>(bufA, gsa_proj_w, bufG, nullptr, 64, 64, 64, 0, 0);
    ln_kernel<<<512, 256>>>(bufG, bufX, ln_c2_w, ln_c2_b, bufA);
    conv1x1_kernel<<<dim3(256, 6, Bn), 256>>>(bufA, ffc_in_w, big1, nullptr, 64, 340, 64, 0, 0);
    dwconv_kernel<<<dim3(64, 340, Bn), 256>>>(big1, ffc_dw_w, big2, 340);
    conv1x1_kernel<<<dim3(256, 1, Bn), 256>>>(big2, ffc_out_w, outp, bufG, HIDn, 64, 340, 0, 1);
}

// round 2
// speedup vs baseline: 1.6666x; 1.6666x over previous
#include <cuda_runtime.h>
#include <math.h>

#define HW   16384
#define Bn   8
#define HIDn 170
#define WSTR 68

// ---------------- scratch (static device memory) ----------------
__device__ float g_bufA[Bn * 64 * HW];
__device__ float g_bufR[Bn * 64 * HW];
__device__ float g_bufX[Bn * 64 * HW];
__device__ float g_bufG[Bn * 64 * HW];
__device__ float g_big1[Bn * 340 * HW];
__device__ float g_big2[Bn * 340 * HW];
__device__ float g_attn[Bn * 8 * 64];
__device__ float g_part[64 * 8 * 80];

__device__ __forceinline__ float gelu_f(float x) {
    return 0.5f * x * (1.0f + erff(x * 0.70710678118654752f));
}

// =================================================================
// conv1x1 (Cin=64) with fused LayerNorm (algebraic) + optional roll
// out[b,o,p] = conv(LN(in + addp))  where LN folded via:
//   y = rs[p]*(Wg@x - mu[p]*Sg[o]) + Sb[o]
// tile: 64 out x 256 px, 256 threads, 8x8 per thread
// =================================================================
__global__ void __launch_bounds__(256, 2)
convln_kernel(const float* __restrict__ in, const float* __restrict__ addp,
              const float* __restrict__ lnw, const float* __restrict__ lnb,
              const float* __restrict__ wt, float* __restrict__ out,
              int Cout, int shift, int useln)
{
    extern __shared__ float sm[];
    float* Xs   = sm;                  // [64][256]
    float* Ws   = sm + 16384;          // [64][68]
    float* mu_s = Ws + 64 * WSTR;      // [256]
    float* rs_s = mu_s + 256;          // [256]
    float* sg_s = rs_s + 256;          // [64]
    float* sb_s = sg_s + 64;           // [64]

    int b = blockIdx.z, p0 = blockIdx.x * 256, o0 = blockIdx.y * 64;
    int tid = threadIdx.x;
    const float* inb = in + (size_t)b * 64 * HW;
    const float* adb = addp ? addp + (size_t)b * 64 * HW : nullptr;

    // ---- stage X ----
    if (shift == 0) {
        #pragma unroll
        for (int i = 0; i < 16; i++) {
            int e4 = i * 256 + tid;
            int c = e4 >> 6, px4 = e4 & 63;
            float4 v = ((const float4*)inb)[((c * HW + p0) >> 2) + px4];
            if (adb) {
                float4 a = ((const float4*)adb)[((c * HW + p0) >> 2) + px4];
                v.x += a.x; v.y += a.y; v.z += a.z; v.w += a.w;
            }
            ((float4*)Xs)[c * 64 + px4] = v;
        }
    } else {
        for (int e = tid; e < 64 * 256; e += 256) {
            int c = e >> 8, px = e & 255;
            int p = p0 + px;
            int h = ((p >> 7) + shift) & 127, w = ((p & 127) + shift) & 127;
            Xs[c * 256 + px] = inb[c * HW + (h << 7) + w];
        }
    }
    // ---- stage W (transposed, x gamma) ----
    for (int e = tid; e < 4096; e += 256) {
        int o = e >> 6, k = e & 63;
        float wv = (o0 + o < Cout) ? wt[(o0 + o) * 64 + k] : 0.f;
        if (useln) wv *= lnw[k];
        Ws[k * WSTR + o] = wv;
    }
    __syncthreads();

    // ---- per-pixel LN stats + per-channel folded constants ----
    if (useln) {
        float s = 0.f;
        #pragma unroll
        for (int c = 0; c < 64; c++) s += Xs[c * 256 + tid];
        float m = s * 0.015625f;
        float v = 0.f;
        #pragma unroll
        for (int c = 0; c < 64; c++) { float d = Xs[c * 256 + tid] - m; v += d * d; }
        mu_s[tid] = m;
        rs_s[tid] = rsqrtf(v * 0.015625f + 1e-5f);
    }
    if (tid < 64) {
        float sg = 0.f, sb = 0.f;
        if (useln) {
            #pragma unroll
            for (int k = 0; k < 64; k++) {
                sg += Ws[k * WSTR + tid];
                sb += ((o0 + tid) < Cout ? wt[(o0 + tid) * 64 + k] : 0.f) * lnb[k];
            }
        }
        sg_s[tid] = sg; sb_s[tid] = sb;
    }
    __syncthreads();

    // ---- GEMM ----
    int to = tid >> 5, tp = tid & 31;
    int ob = to << 3, pb = tp << 3;
    float acc[8][8] = {};
    const float* XsP = Xs + pb;
    const float* WsP = Ws + ob;
    #pragma unroll 4
    for (int k = 0; k < 64; k++) {
        float4 w0 = *(const float4*)(WsP + k * WSTR);
        float4 w1 = *(const float4*)(WsP + k * WSTR + 4);
        float4 x0 = *(const float4*)(XsP + k * 256);
        float4 x1 = *(const float4*)(XsP + k * 256 + 4);
        float wr[8] = {w0.x, w0.y, w0.z, w0.w, w1.x, w1.y, w1.z, w1.w};
        float xr[8] = {x0.x, x0.y, x0.z, x0.w, x1.x, x1.y, x1.z, x1.w};
        #pragma unroll
        for (int i = 0; i < 8; i++)
            #pragma unroll
            for (int j = 0; j < 8; j++)
                acc[i][j] += wr[i] * xr[j];
    }

    // ---- epilogue ----
    float mur[8], rsr[8];
    if (useln) {
        #pragma unroll
        for (int j = 0; j < 8; j++) { mur[j] = mu_s[pb + j]; rsr[j] = rs_s[pb + j]; }
    }
    #pragma unroll
    for (int i = 0; i < 8; i++) {
        int o = o0 + ob + i;
        if (o < Cout) {
            float* op = out + ((size_t)b * Cout + o) * HW + p0 + pb;
            float r[8];
            if (useln) {
                float sg = sg_s[ob + i], sb = sb_s[ob + i];
                #pragma unroll
                for (int j = 0; j < 8; j++) r[j] = rsr[j] * (acc[i][j] - mur[j] * sg) + sb;
            } else {
                #pragma unroll
                for (int j = 0; j < 8; j++) r[j] = acc[i][j];
            }
            *(float4*)op       = make_float4(r[0], r[1], r[2], r[3]);
            *(float4*)(op + 4) = make_float4(r[4], r[5], r[6], r[7]);
        }
    }
}

// =================================================================
// gated conv1x1: out = W @ (gelu(x1)*x2) + resid ; Cin=170 (phys 340)
// =================================================================
#define GK 34
__global__ void __launch_bounds__(256, 2)
convgate_kernel(const float* __restrict__ in, const float* __restrict__ wt,
                float* __restrict__ out, const float* __restrict__ resid)
{
    __shared__ float Xs[GK * 256];
    __shared__ float Ws[GK * WSTR];
    int b = blockIdx.z, p0 = blockIdx.x * 256;
    int tid = threadIdx.x;
    const float* inb = in + (size_t)b * 340 * HW;
    int to = tid >> 5, tp = tid & 31;
    int ob = to << 3, pb = tp << 3;
    float acc[8][8] = {};

    for (int kt = 0; kt < 5; kt++) {
        __syncthreads();
        for (int e = tid; e < GK * 256; e += 256) {
            int kk = e >> 8, px = e & 255;
            int c = kt * GK + kk;
            float a = inb[(size_t)c * HW + p0 + px];
            float g = inb[(size_t)(c + HIDn) * HW + p0 + px];
            Xs[kk * 256 + px] = gelu_f(a) * g;
        }
        for (int e = tid; e < GK * 64; e += 256) {
            int o = e / GK, kk = e - o * GK;
            Ws[kk * WSTR + o] = wt[o * HIDn + kt * GK + kk];
        }
        __syncthreads();
        const float* XsP = Xs + pb;
        const float* WsP = Ws + ob;
        #pragma unroll 2
        for (int k = 0; k < GK; k++) {
            float4 w0 = *(const float4*)(WsP + k * WSTR);
            float4 w1 = *(const float4*)(WsP + k * WSTR + 4);
            float4 x0 = *(const float4*)(XsP + k * 256);
            float4 x1 = *(const float4*)(XsP + k * 256 + 4);
            float wr[8] = {w0.x, w0.y, w0.z, w0.w, w1.x, w1.y, w1.z, w1.w};
            float xr[8] = {x0.x, x0.y, x0.z, x0.w, x1.x, x1.y, x1.z, x1.w};
            #pragma unroll
            for (int i = 0; i < 8; i++)
                #pragma unroll
                for (int j = 0; j < 8; j++)
                    acc[i][j] += wr[i] * xr[j];
        }
    }
    #pragma unroll
    for (int i = 0; i < 8; i++) {
        int o = ob + i;
        const float* rp = resid + ((size_t)b * 64 + o) * HW + p0 + pb;
        float* op = out + ((size_t)b * 64 + o) * HW + p0 + pb;
        float4 r0 = *(const float4*)rp;
        float4 r1 = *(const float4*)(rp + 4);
        *(float4*)op       = make_float4(acc[i][0] + r0.x, acc[i][1] + r0.y, acc[i][2] + r0.z, acc[i][3] + r0.w);
        *(float4*)(op + 4) = make_float4(acc[i][4] + r1.x, acc[i][5] + r1.y, acc[i][6] + r1.z, acc[i][7] + r1.w);
    }
}

// ---------------- depthwise 3x3 conv, zero padding, 4 px/thread ----------------
__global__ void dwconv_kernel(const float* __restrict__ in, const float* __restrict__ wt,
                              float* __restrict__ out, int Ch)
{
    int c = blockIdx.y, b = blockIdx.z;
    int p = (blockIdx.x * 256 + threadIdx.x) << 2;
    int h = p >> 7, w0 = p & 127;
    const float* ib = in + ((size_t)b * Ch + c) * HW;
    const float* wc = wt + c * 9;
    float acc[4] = {0.f, 0.f, 0.f, 0.f};
    #pragma unroll
    for (int dy = -1; dy <= 1; dy++) {
        int hh = h + dy;
        if ((unsigned)hh > 127u) continue;
        const float* row = ib + (hh << 7);
        float4 mid = *(const float4*)(row + w0);
        float r0 = (w0 > 0)   ? row[w0 - 1] : 0.f;
        float r5 = (w0 < 124) ? row[w0 + 4] : 0.f;
        float r[6] = {r0, mid.x, mid.y, mid.z, mid.w, r5};
        float wa = wc[(dy + 1) * 3 + 0], wb = wc[(dy + 1) * 3 + 1], wcc = wc[(dy + 1) * 3 + 2];
        #pragma unroll
        for (int j = 0; j < 4; j++)
            acc[j] += wa * r[j] + wb * r[j + 1] + wcc * r[j + 2];
    }
    *(float4*)(out + ((size_t)b * Ch + c) * HW + p) = make_float4(acc[0], acc[1], acc[2], acc[3]);
}

// =================================================================
// RSA window attention, one 8x8 window (64 px x 64 ch) per block
// =================================================================
__global__ void __launch_bounds__(256, 4)
rsa_attn_kernel(const float* __restrict__ qkv, float* __restrict__ out,
                const float* __restrict__ temp)
{
    extern __shared__ float sm[];
    float* A   = sm;                    // q as [p][c], later v as [c][p]
    float* B   = sm + 64 * WSTR;        // k as [p][c], later out as [d][p]
    float* C   = sm + 2 * 64 * WSTR;    // attn as [c][d]
    float* inv = sm + 3 * 64 * WSTR;    // [64]
    int blk = blockIdx.x;
    int b = blk >> 8, win = blk & 255;
    int wy = win >> 4, wx = win & 15;
    int tid = threadIdx.x;
    size_t qbase = (size_t)b * 192 * HW;

    // load q,k: [p][c]
    for (int e = tid; e < 4096; e += 256) {
        int p = e & 63, c = e >> 6;
        int gp = (((wy << 3) + (p >> 3)) << 7) | ((wx << 3) + (p & 7));
        A[p * WSTR + c] = qkv[qbase + c * HW + gp];
        B[p * WSTR + c] = qkv[qbase + (64 + c) * HW + gp];
    }
    __syncthreads();
    if (tid < 64) {
        int p = tid;
        float nq = 0.f, nk = 0.f;
        #pragma unroll
        for (int c = 0; c < 64; c++) {
            float a = A[p * WSTR + c]; nq += a * a;
            float bb = B[p * WSTR + c]; nk += bb * bb;
        }
        inv[p] = 1.0f / (fmaxf(sqrtf(nq), 1e-12f) * fmaxf(sqrtf(nk), 1e-12f));
    }
    __syncthreads();
    // fold both norms into k rows
    for (int e4 = tid; e4 < 1024; e4 += 256) {
        int p = e4 >> 4, c4 = e4 & 15;
        float iv = inv[p];
        float4 v = ((float4*)B)[p * (WSTR / 4) + c4];
        v.x *= iv; v.y *= iv; v.z *= iv; v.w *= iv;
        ((float4*)B)[p * (WSTR / 4) + c4] = v;
    }
    __syncthreads();
    float tscale = temp[0];
    // GEMM1: attn[c,d] = relu(t * sum_p q[p,c] k[p,d])
    {
        int c0 = (tid >> 4) << 2, d0 = (tid & 15) << 2;
        float s[4][4] = {};
        #pragma unroll 4
        for (int p = 0; p < 64; p++) {
            float4 qv = *(const float4*)(A + p * WSTR + c0);
            float4 kv = *(const float4*)(B + p * WSTR + d0);
            float qr[4] = {qv.x, qv.y, qv.z, qv.w};
            float kr[4] = {kv.x, kv.y, kv.z, kv.w};
            #pragma unroll
            for (int i = 0; i < 4; i++)
                #pragma unroll
                for (int j = 0; j < 4; j++) s[i][j] += qr[i] * kr[j];
        }
        #pragma unroll
        for (int i = 0; i < 4; i++)
            *(float4*)(C + (c0 + i) * WSTR + d0) =
                make_float4(fmaxf(0.f, tscale * s[i][0]), fmaxf(0.f, tscale * s[i][1]),
                            fmaxf(0.f, tscale * s[i][2]), fmaxf(0.f, tscale * s[i][3]));
    }
    __syncthreads();
    // load v: [c][p]
    for (int e = tid; e < 4096; e += 256) {
        int p = e & 63, c = e >> 6;
        int gp = (((wy << 3) + (p >> 3)) << 7) | ((wx << 3) + (p & 7));
        A[c * WSTR + p] = qkv[qbase + (128 + c) * HW + gp];
    }
    __syncthreads();
    // GEMM2: out[p,d] = sum_c v[c,p] attn[c,d] -> stage into B as [d][p]
    {
        int p0 = (tid >> 4) << 2, d0 = (tid & 15) << 2;
        float s[4][4] = {};
        #pragma unroll 4
        for (int c = 0; c < 64; c++) {
            float4 vv = *(const float4*)(A + c * WSTR + p0);
            float4 av = *(const float4*)(C + c * WSTR + d0);
            float vr[4] = {vv.x, vv.y, vv.z, vv.w};
            float ar[4] = {av.x, av.y, av.z, av.w};
            #pragma unroll
            for (int i = 0; i < 4; i++)
                #pragma unroll
                for (int j = 0; j < 4; j++) s[i][j] += vr[i] * ar[j];
        }
        #pragma unroll
        for (int j = 0; j < 4; j++)
            *(float4*)(B + (d0 + j) * WSTR + p0) = make_float4(s[0][j], s[1][j], s[2][j], s[3][j]);
    }
    __syncthreads();
    size_t obase = (size_t)b * 64 * HW;
    for (int e = tid; e < 4096; e += 256) {
        int p = e & 63, d = e >> 6;
        int gp = (((wy << 3) + (p >> 3)) << 7) | ((wx << 3) + (p & 7));
        out[obase + d * HW + gp] = B[d * WSTR + p];
    }
}

// ---------------- GSA: partial Gram sums (chunked) -------------------------------
__global__ void gsa_attn_part(const float* __restrict__ qkv, float* __restrict__ part)
{
    __shared__ float red[8][80];
    int bh = blockIdx.y;
    int b = bh >> 3, hd = bh & 7;
    int chunk = blockIdx.x;
    int tid = threadIdx.x;
    const float* qb = qkv + ((size_t)b * 192 + hd * 8) * HW;
    const float* kb = qkv + ((size_t)b * 192 + 64 + hd * 8) * HW;
    float dot[8][8] = {};
    float qn[8] = {}, kn[8] = {};
    int n0 = chunk * 2048;
    for (int n = n0 + tid; n < n0 + 2048; n += 256) {
        float qv[8], kv[8];
        #pragma unroll
        for (int i = 0; i < 8; i++) { qv[i] = qb[i * HW + n]; kv[i] = kb[i * HW + n]; }
        #pragma unroll
        for (int i = 0; i < 8; i++) { qn[i] += qv[i] * qv[i]; kn[i] += kv[i] * kv[i]; }
        #pragma unroll
        for (int i = 0; i < 8; i++)
            #pragma unroll
            for (int j = 0; j < 8; j++) dot[i][j] += qv[i] * kv[j];
    }
    int lane = tid & 31, w = tid >> 5;
    #pragma unroll
    for (int i = 0; i < 8; i++)
        #pragma unroll
        for (int j = 0; j < 8; j++) {
            float v = dot[i][j];
            #pragma unroll
            for (int off = 16; off; off >>= 1) v += __shfl_xor_sync(0xffffffffu, v, off);
            if (lane == 0) red[w][i * 8 + j] = v;
        }
    #pragma unroll
    for (int i = 0; i < 8; i++) {
        float v = qn[i];
        #pragma unroll
        for (int off = 16; off; off >>= 1) v += __shfl_xor_sync(0xffffffffu, v, off);
        if (lane == 0) red[w][64 + i] = v;
        float u = kn[i];
        #pragma unroll
        for (int off = 16; off; off >>= 1) u += __shfl_xor_sync(0xffffffffu, u, off);
        if (lane == 0) red[w][72 + i] = u;
    }
    __syncthreads();
    if (tid < 80) {
        float s = 0.f;
        #pragma unroll
        for (int w2 = 0; w2 < 8; w2++) s += red[w2][tid];
        part[((size_t)bh * 8 + chunk) * 80 + tid] = s;
    }
}

__global__ void gsa_attn_final(const float* __restrict__ part, float* __restrict__ attn,
                               const float* __restrict__ temp)
{
    __shared__ float fin[80];
    int bh = blockIdx.x, tid = threadIdx.x;
    if (tid < 80) {
        float s = 0.f;
        #pragma unroll
        for (int c = 0; c < 8; c++) s += part[((size_t)bh * 8 + c) * 80 + tid];
        fin[tid] = s;
    }
    __syncthreads();
    if (tid < 64) {
        int c = tid >> 3, d = tid & 7;
        float nq = fmaxf(sqrtf(fin[64 + c]), 1e-12f);
        float nk = fmaxf(sqrtf(fin[72 + d]), 1e-12f);
        attn[(size_t)bh * 64 + tid] = fmaxf(0.f, temp[0] * fin[tid] / (nq * nk));
    }
}

// ---------------- GSA: apply attention, (head,c)->(c*8+head) reorder -------------
__global__ void gsa_apply_kernel(const float* __restrict__ qkv, const float* __restrict__ attn,
                                 float* __restrict__ out)
{
    __shared__ float at[512];
    int b = blockIdx.y;
    int tid = threadIdx.x;
    for (int e = tid; e < 512; e += 256) at[e] = attn[b * 512 + e];
    __syncthreads();
    int n = blockIdx.x * 256 + tid;
    const float* vb = qkv + ((size_t)b * 192 + 128) * HW + n;
    float* ob = out + (size_t)b * 64 * HW + n;
    #pragma unroll
    for (int hd = 0; hd < 8; hd++) {
        float vv[8];
        #pragma unroll
        for (int d = 0; d < 8; d++) vv[d] = vb[(hd * 8 + d) * HW];
        #pragma unroll
        for (int cc = 0; cc < 8; cc++) {
            float s = 0.f;
            #pragma unroll
            for (int d = 0; d < 8; d++) s += at[hd * 64 + cc * 8 + d] * vv[d];
            ob[(cc * 8 + hd) * HW] = s;
        }
    }
}

// ---------------- launch ---------------------------------------------------------
extern "C" void kernel_launch(void* const* d_in, const int* in_sizes, int n_in,
                              void* d_out, int out_size)
{
    const float* x         = (const float*)d_in[0];
    const float* ln_s0_w   = (const float*)d_in[1];
    const float* ln_s0_b   = (const float*)d_in[2];
    const float* ln_s2_w   = (const float*)d_in[3];
    const float* ln_s2_b   = (const float*)d_in[4];
    const float* rsa_qkv_w = (const float*)d_in[5];
    const float* rsa_dw_w  = (const float*)d_in[6];
    const float* rsa_proj_w= (const float*)d_in[7];
    const float* rsa_temp  = (const float*)d_in[8];
    const float* ffs_in_w  = (const float*)d_in[9];
    const float* ffs_dw_w  = (const float*)d_in[10];
    const float* ffs_out_w = (const float*)d_in[11];
    const float* ln_c0_w   = (const float*)d_in[12];
    const float* ln_c0_b   = (const float*)d_in[13];
    const float* ln_c2_w   = (const float*)d_in[14];
    const float* ln_c2_b   = (const float*)d_in[15];
    const float* gsa_qkv_w = (const float*)d_in[16];
    const float* gsa_dw_w  = (const float*)d_in[17];
    const float* gsa_proj_w= (const float*)d_in[18];
    const float* gsa_temp  = (const float*)d_in[19];
    const float* ffc_in_w  = (const float*)d_in[20];
    const float* ffc_dw_w  = (const float*)d_in[21];
    const float* ffc_out_w = (const float*)d_in[22];
    float* outp = (float*)d_out;

    float *bufA, *bufR, *bufX, *bufG, *big1, *big2, *attnb, *partb;
    cudaGetSymbolAddress((void**)&bufA,  g_bufA);
    cudaGetSymbolAddress((void**)&bufR,  g_bufR);
    cudaGetSymbolAddress((void**)&bufX,  g_bufX);
    cudaGetSymbolAddress((void**)&bufG,  g_bufG);
    cudaGetSymbolAddress((void**)&big1,  g_big1);
    cudaGetSymbolAddress((void**)&big2,  g_big2);
    cudaGetSymbolAddress((void**)&attnb, g_attn);
    cudaGetSymbolAddress((void**)&partb, g_part);

    const int convln_smem = (16384 + 64 * WSTR + 256 + 256 + 64 + 64) * (int)sizeof(float);
    const int rsa_smem    = (3 * 64 * WSTR + 64) * (int)sizeof(float);
    cudaFuncSetAttribute(convln_kernel, cudaFuncAttributeMaxDynamicSharedMemorySize, convln_smem);
    cudaFuncSetAttribute(rsa_attn_kernel, cudaFuncAttributeMaxDynamicSharedMemorySize, rsa_smem);

    // ---- stage 1: RSA + spatial FFN ----
    convln_kernel<<<dim3(64, 3, Bn), 256, convln_smem>>>(x, nullptr, ln_s0_w, ln_s0_b, rsa_qkv_w, big1, 192,  4, 1);
    dwconv_kernel<<<dim3(16, 192, Bn), 256>>>(big1, rsa_dw_w, big2, 192);
    rsa_attn_kernel<<<Bn * 256, 256, rsa_smem>>>(big2, bufA, rsa_temp);
    convln_kernel<<<dim3(64, 1, Bn), 256, convln_smem>>>(bufA, nullptr, nullptr, nullptr, rsa_proj_w, bufR, 64, -4, 0);
    convln_kernel<<<dim3(64, 6, Bn), 256, convln_smem>>>(bufR, x, ln_s2_w, ln_s2_b, ffs_in_w, big1, 340, 0, 1);
    dwconv_kernel<<<dim3(16, 340, Bn), 256>>>(big1, ffs_dw_w, big2, 340);
    convgate_kernel<<<dim3(64, 1, Bn), 256>>>(big2, ffs_out_w, bufX, bufR);

    // ---- stage 2: GSA + channel FFN ----
    convln_kernel<<<dim3(64, 3, Bn), 256, convln_smem>>>(bufX, nullptr, ln_c0_w, ln_c0_b, gsa_qkv_w, big1, 192, 0, 1);
    dwconv_kernel<<<dim3(16, 192, Bn), 256>>>(big1, gsa_dw_w, big2, 192);
    gsa_attn_part<<<dim3(8, 64), 256>>>(big2, partb);
    gsa_attn_final<<<64, 128>>>(partb, attnb, gsa_temp);
    gsa_apply_kernel<<<dim3(64, Bn), 256>>>(big2, attnb, bufA);
    convln_kernel<<<dim3(64, 1, Bn), 256, convln_smem>>>(bufA, nullptr, nullptr, nullptr, gsa_proj_w, bufG, 64, 0, 0);
    convln_kernel<<<dim3(64, 6, Bn), 256, convln_smem>>>(bufG, bufX, ln_c2_w, ln_c2_b, ffc_in_w, big1, 340, 0, 1);
    dwconv_kernel<<<dim3(16, 340, Bn), 256>>>(big1, ffc_dw_w, big2, 340);
    convgate_kernel<<<dim3(64, 1, Bn), 256>>>(big2, ffc_out_w, outp, bufG);
}